// round 8
// baseline (speedup 1.0000x reference)
#include <cuda_runtime.h>
#include <cuda_bf16.h>
#include <cstdint>

// One-hot expansion: mask [1,1,256,256,48] fp32 integer labels 0..40
//   -> out [1,40,256,256,48], out[:,c] = (mask == c+1) ? 1.0f : 0.0f
//
// Write-stream locality experiment: previous kernels had every CTA writing
// 40 interleaved streams (47k chip-wide open write regions). Here each CTA
// owns ONE channel (blockIdx.y) and one contiguous 32KB output chunk, so
// concurrent write streams drop to ~#CTAs, each perfectly sequential.
// Cost: mask is re-read once per channel (40 x 12.6MB = 503MB of L2 reads),
// but the 12.6MB mask is L2-resident; DRAM read traffic stays 12.6MB.
// Launch order (x fastest) sweeps channel 0 first, priming L2 with the mask.

#define N_LABELS 40
#define F4_PER_THREAD 8   // 256 thr * 8 = 2048 float4 = 32KB per CTA

__global__ __launch_bounds__(256)
void onehot40_kernel(const float4* __restrict__ mask4,
                     float4* __restrict__ out4,
                     int vol4) {
    const int   c    = blockIdx.y;
    const float lab  = (float)(c + 1);
    const int   i0   = blockIdx.x * (256 * F4_PER_THREAD) + threadIdx.x;
    float4* __restrict__ oc = out4 + (size_t)c * (size_t)vol4;

#pragma unroll
    for (int j = 0; j < F4_PER_THREAD; j++) {
        int i = i0 + j * 256;                 // warp-contiguous lanes
        float4 m = __ldg(&mask4[i]);          // L2 hit after channel-0 wave
        float4 r;
        r.x = (m.x == lab) ? 1.0f : 0.0f;
        r.y = (m.y == lab) ? 1.0f : 0.0f;
        r.z = (m.z == lab) ? 1.0f : 0.0f;
        r.w = (m.w == lab) ? 1.0f : 0.0f;
        oc[i] = r;
    }
}

extern "C" void kernel_launch(void* const* d_in, const int* in_sizes, int n_in,
                              void* d_out, int out_size) {
    const float* mask = (const float*)d_in[0];
    float* out = (float*)d_out;

    int vol  = in_sizes[0];         // 3,145,728
    int vol4 = vol / 4;             // 786,432 = 384 * 2048 exactly

    dim3 grid(vol4 / (256 * F4_PER_THREAD), N_LABELS);  // (384, 40)
    onehot40_kernel<<<grid, 256>>>(
        (const float4*)mask, (float4*)out, vol4);
}

// round 9
// speedup vs baseline: 1.0127x; 1.0127x over previous
#include <cuda_runtime.h>
#include <cuda_bf16.h>
#include <cstdint>

// One-hot expansion: mask [1,1,256,256,48] fp32 integer labels 0..40
//   -> out [1,40,256,256,48], out[:,c] = (mask == c+1) ? 1.0f : 0.0f
//
// CONVERGED: streaming-store bound at the HBM write ceiling (~5.8 TB/s
// measured, invariant across L2 policy hints [R6], store MLP [R7],
// occupancy 52-88% [R6/R7], and write-stream locality [R8]).
// 516 MB mandatory traffic / 5.8 TB/s ~= 80 us floor.
//
// Layout (best measured, R1): thread t owns float4 t; each warp STG.128
// covers a contiguous 512B span (4 full 128B lines). Grid divides the
// volume exactly (786,432 float4 = 3072 x 256), so no bounds check; the
// channel loop is 40 constant-offset stores off one base pointer.

#define N_LABELS 40

__global__ __launch_bounds__(256)
void onehot40_kernel(const float4* __restrict__ mask4,
                     float4* __restrict__ out4,
                     int vol4) {
    int i = blockIdx.x * blockDim.x + threadIdx.x;   // always < vol4 (exact grid)

    float4 m = mask4[i];
    float4* __restrict__ o = out4 + i;

#pragma unroll
    for (int c = 0; c < N_LABELS; c++) {
        const float lab = (float)(c + 1);
        float4 r;
        r.x = (m.x == lab) ? 1.0f : 0.0f;
        r.y = (m.y == lab) ? 1.0f : 0.0f;
        r.z = (m.z == lab) ? 1.0f : 0.0f;
        r.w = (m.w == lab) ? 1.0f : 0.0f;
        o[(size_t)c * (size_t)vol4] = r;
    }
}

extern "C" void kernel_launch(void* const* d_in, const int* in_sizes, int n_in,
                              void* d_out, int out_size) {
    const float* mask = (const float*)d_in[0];
    float* out = (float*)d_out;

    int vol  = in_sizes[0];         // 256*256*48 = 3,145,728
    int vol4 = vol / 4;             // 786,432 = 3072 * 256 exactly

    onehot40_kernel<<<vol4 / 256, 256>>>(
        (const float4*)mask, (float4*)out, vol4);
}